// round 4
// baseline (speedup 1.0000x reference)
#include <cuda_runtime.h>
#include <cstdint>

#define B_SAMPLES 65536
#define F_DIM 512
#define H_DIM 90
#define D_IN 602
#define N1 128
#define N2 256
#define N_OUT 9
#define ALPHA 0.9f
#define BETA 0.8f
#define T_STEPS 10

// 32 MB scratch for loop-invariant h1 = x @ W1^T + b1   (allowed: __device__ global)
__device__ float g_h1[(size_t)B_SAMPLES * N1];

// ---------------------------------------------------------------------------
// Kernel 1: h1 = [state | history] @ W1^T + b1        (fp32 SGEMM, exact)
//   M = 65536, N = 128, K = 602
// ---------------------------------------------------------------------------
#define BM 128
#define BN 128
#define BK 8
#define TM 8
#define TN 8
#define APAD 4

__global__ __launch_bounds__(256, 2)
void gemm_h1_kernel(const float* __restrict__ state,
                    const float* __restrict__ history,
                    const float* __restrict__ W1,
                    const float* __restrict__ b1)
{
    __shared__ float As[BK][BM + APAD];
    __shared__ float Bs[BK][BN + APAD];

    const int tid = threadIdx.x;
    const int tx  = tid & 15;        // 0..15 -> N direction
    const int ty  = tid >> 4;        // 0..15 -> M direction
    const int m0  = blockIdx.x * BM;

    float acc[TM][TN];
#pragma unroll
    for (int i = 0; i < TM; i++)
#pragma unroll
        for (int j = 0; j < TN; j++) acc[i][j] = 0.0f;

    for (int k0 = 0; k0 < D_IN; k0 += BK) {
        // Load A tile: x[m0+m][k0+k], concat of state / history on the fly.
#pragma unroll
        for (int l = 0; l < 4; l++) {
            int e = tid + l * 256;          // 0..1023
            int m = e >> 3;
            int k = e & 7;
            int g = k0 + k;
            float v = 0.0f;
            int gm = m0 + m;
            if (g < F_DIM)      v = state[(size_t)gm * F_DIM + g];
            else if (g < D_IN)  v = history[(size_t)gm * H_DIM + (g - F_DIM)];
            As[k][m] = v;
        }
        // Load B tile: W1[n][k0+k]  (row-major [128][602])
#pragma unroll
        for (int l = 0; l < 4; l++) {
            int e = tid + l * 256;
            int n = e >> 3;
            int k = e & 7;
            int g = k0 + k;
            float v = 0.0f;
            if (g < D_IN) v = W1[(size_t)n * D_IN + g];
            Bs[k][n] = v;
        }
        __syncthreads();

#pragma unroll
        for (int k = 0; k < BK; k++) {
            float ra[TM], rb[TN];
#pragma unroll
            for (int i = 0; i < TM; i++) ra[i] = As[k][ty * TM + i];
#pragma unroll
            for (int j = 0; j < TN; j++) rb[j] = Bs[k][tx * TN + j];
#pragma unroll
            for (int i = 0; i < TM; i++)
#pragma unroll
                for (int j = 0; j < TN; j++)
                    acc[i][j] = fmaf(ra[i], rb[j], acc[i][j]);
        }
        __syncthreads();
    }

    // Epilogue: add bias, store to scratch
#pragma unroll
    for (int i = 0; i < TM; i++) {
        int m = m0 + ty * TM + i;
        float* dst = &g_h1[(size_t)m * N1 + tx * TN];
#pragma unroll
        for (int j = 0; j < TN; j++)
            dst[j] = acc[i][j] + b1[tx * TN + j];
    }
}

// ---------------------------------------------------------------------------
// Kernel 2: 10-step LIF recurrence, warp-per-sample, delta-encoded spike GEMVs
// ---------------------------------------------------------------------------
#define K2_THREADS 512
#define W2_STRIDE 264    // 256 cols padded to 264 floats (32B-aligned rows)

__global__ __launch_bounds__(K2_THREADS, 1)
void snn_steps_kernel(const float* __restrict__ W2,
                      const float* __restrict__ b2,
                      const float* __restrict__ W3,
                      const float* __restrict__ b3,
                      float* __restrict__ out)
{
    extern __shared__ float sm[];
    float* W2c = sm;                                  // [128][264] column-major of W2
    float* W3c = sm + (size_t)N1 * W2_STRIDE;          // [256][9]   column-major of W3

    const int tid = threadIdx.x;

    // Stage W2:  W2[j*128 + i]  ->  W2c[i*264 + j]   (coalesced global reads)
    for (int idx = tid; idx < N1 * N2; idx += K2_THREADS) {
        int i = idx & (N1 - 1);
        int j = idx >> 7;
        W2c[i * W2_STRIDE + j] = W2[idx];
    }
    // Stage W3:  W3[k*256 + j]  ->  W3c[j*9 + k]
    for (int idx = tid; idx < N2 * N_OUT; idx += K2_THREADS) {
        int k = idx >> 8;
        int j = idx & (N2 - 1);
        W3c[j * N_OUT + k] = W3[idx];
    }
    __syncthreads();

    const int lane   = tid & 31;
    const int warp   = tid >> 5;
    const int gwarp  = blockIdx.x * (K2_THREADS / 32) + warp;
    const int nwarps = gridDim.x * (K2_THREADS / 32);

    const float4* b2v = reinterpret_cast<const float4*>(b2);

    for (int s = gwarp; s < B_SAMPLES; s += nwarps) {
        // ---- Layer 1 state: 4 neurons per lane, neuron i = q*32 + lane ----
        float h1v[4], mem1[4], syn1[4];
#pragma unroll
        for (int q = 0; q < 4; q++) {
            h1v[q]  = g_h1[(size_t)s * N1 + q * 32 + lane];
            mem1[q] = 0.0f;
            syn1[q] = 0.0f;
        }
        unsigned prev1[4] = {0u, 0u, 0u, 0u};

        // ---- Layer 2 state: 8 neurons per lane, neuron j = lane*8 + r ----
        float h2a[8], mem2[8], syn2[8];
        float4 bb0 = b2v[lane * 2];
        float4 bb1 = b2v[lane * 2 + 1];
        h2a[0] = bb0.x; h2a[1] = bb0.y; h2a[2] = bb0.z; h2a[3] = bb0.w;
        h2a[4] = bb1.x; h2a[5] = bb1.y; h2a[6] = bb1.z; h2a[7] = bb1.w;
#pragma unroll
        for (int r = 0; r < 8; r++) { mem2[r] = 0.0f; syn2[r] = 0.0f; }
        unsigned prev2[8] = {0u,0u,0u,0u,0u,0u,0u,0u};

        // ---- Layer 3 state: lanes 0..8 each own one output ----
        float h3a = (lane < N_OUT) ? b3[lane] : 0.0f;
        float syn3 = 0.0f, mem3 = 0.0f, pot = 0.0f;

        for (int t = 0; t < T_STEPS; t++) {
            // LIF layer 1
            unsigned cur1[4];
#pragma unroll
            for (int q = 0; q < 4; q++) {
                syn1[q] = fmaf(ALPHA, syn1[q], h1v[q]);
                mem1[q] = fmaf(BETA,  mem1[q], syn1[q]);
                bool sp = (mem1[q] - 1.0f) > 0.0f;
                cur1[q] = __ballot_sync(0xffffffffu, sp);
                if (sp) mem1[q] -= 1.0f;
            }

            // Delta update of h2acc = b2 + W2 @ spk1 (sparse column add/sub)
#pragma unroll
            for (int q = 0; q < 4; q++) {
                unsigned addm = cur1[q] & ~prev1[q];
                unsigned subm = prev1[q] & ~cur1[q];
                prev1[q] = cur1[q];
                while (addm) {
                    int i = __ffs(addm) - 1; addm &= addm - 1;
                    const float4* col = reinterpret_cast<const float4*>(
                        &W2c[(q * 32 + i) * W2_STRIDE + lane * 8]);
                    float4 a = col[0], b = col[1];
                    h2a[0] += a.x; h2a[1] += a.y; h2a[2] += a.z; h2a[3] += a.w;
                    h2a[4] += b.x; h2a[5] += b.y; h2a[6] += b.z; h2a[7] += b.w;
                }
                while (subm) {
                    int i = __ffs(subm) - 1; subm &= subm - 1;
                    const float4* col = reinterpret_cast<const float4*>(
                        &W2c[(q * 32 + i) * W2_STRIDE + lane * 8]);
                    float4 a = col[0], b = col[1];
                    h2a[0] -= a.x; h2a[1] -= a.y; h2a[2] -= a.z; h2a[3] -= a.w;
                    h2a[4] -= b.x; h2a[5] -= b.y; h2a[6] -= b.z; h2a[7] -= b.w;
                }
            }

            // LIF layer 2
            unsigned cur2[8];
#pragma unroll
            for (int r = 0; r < 8; r++) {
                syn2[r] = fmaf(ALPHA, syn2[r], h2a[r]);
                mem2[r] = fmaf(BETA,  mem2[r], syn2[r]);
                bool sp = (mem2[r] - 1.0f) > 0.0f;
                cur2[r] = __ballot_sync(0xffffffffu, sp);
                if (sp) mem2[r] -= 1.0f;
            }

            // Delta update of h3acc = b3 + W3 @ spk2 (lanes 0..8 accumulate)
#pragma unroll
            for (int r = 0; r < 8; r++) {
                unsigned addm = cur2[r] & ~prev2[r];
                unsigned subm = prev2[r] & ~cur2[r];
                prev2[r] = cur2[r];
                while (addm) {
                    int l = __ffs(addm) - 1; addm &= addm - 1;
                    if (lane < N_OUT) h3a += W3c[(l * 8 + r) * N_OUT + lane];
                }
                while (subm) {
                    int l = __ffs(subm) - 1; subm &= subm - 1;
                    if (lane < N_OUT) h3a -= W3c[(l * 8 + r) * N_OUT + lane];
                }
            }

            // Layer 3 integrate (no spike)
            syn3 = fmaf(ALPHA, syn3, h3a);
            mem3 = fmaf(BETA,  mem3, syn3);
            pot += mem3;
        }

        if (lane < N_OUT)
            out[(size_t)s * N_OUT + lane] = pot * (1.0f / T_STEPS);
    }
}

// ---------------------------------------------------------------------------
// Launch
// ---------------------------------------------------------------------------
extern "C" void kernel_launch(void* const* d_in, const int* in_sizes, int n_in,
                              void* d_out, int out_size)
{
    const float* state   = (const float*)d_in[0];
    const float* history = (const float*)d_in[1];
    const float* W1      = (const float*)d_in[2];
    const float* b1      = (const float*)d_in[3];
    const float* W2      = (const float*)d_in[4];
    const float* b2      = (const float*)d_in[5];
    const float* W3      = (const float*)d_in[6];
    const float* b3      = (const float*)d_in[7];
    float* out = (float*)d_out;

    // K1: h1 GEMM
    gemm_h1_kernel<<<B_SAMPLES / BM, 256>>>(state, history, W1, b1);

    // K2: recurrent SNN steps (needs 144,384 B dynamic SMEM -> opt-in)
    const size_t smem_bytes = ((size_t)N1 * W2_STRIDE + (size_t)N2 * N_OUT) * sizeof(float);
    static bool attr_set = false;  // idempotent attribute set (not a guard on work)
    if (!attr_set) {
        cudaFuncSetAttribute(snn_steps_kernel,
                             cudaFuncAttributeMaxDynamicSharedMemorySize,
                             (int)smem_bytes);
        attr_set = true;
    }
    snn_steps_kernel<<<148, K2_THREADS, smem_bytes>>>(W2, b2, W3, b3, out);
}

// round 5
// speedup vs baseline: 1.1428x; 1.1428x over previous
#include <cuda_runtime.h>
#include <cstdint>

#define B_SAMPLES 65536
#define F_DIM 512
#define H_DIM 90
#define D_IN 602
#define N1 128
#define N2 256
#define N_OUT 9
#define ALPHA 0.9f
#define BETA 0.8f
#define T_STEPS 10

// 32 MB scratch for loop-invariant h1 = x @ W1^T + b1
__device__ float g_h1[(size_t)B_SAMPLES * N1];
// Packed layer-1 spike raster: per (sample, step) one uint4 = 128 spike bits.
__device__ uint4 g_spk[(size_t)B_SAMPLES * T_STEPS];

// ---------------------------------------------------------------------------
// Kernel 1: h1 = [state | history] @ W1^T + b1        (fp32 SGEMM, exact)
//   M = 65536, N = 128, K = 602
// ---------------------------------------------------------------------------
#define BM 128
#define BN 128
#define BK 8
#define TM 8
#define TN 8
#define APAD 4

__global__ __launch_bounds__(256, 2)
void gemm_h1_kernel(const float* __restrict__ state,
                    const float* __restrict__ history,
                    const float* __restrict__ W1,
                    const float* __restrict__ b1)
{
    __shared__ float As[BK][BM + APAD];
    __shared__ float Bs[BK][BN + APAD];

    const int tid = threadIdx.x;
    const int tx  = tid & 15;        // N direction
    const int ty  = tid >> 4;        // M direction
    const int m0  = blockIdx.x * BM;

    float acc[TM][TN];
#pragma unroll
    for (int i = 0; i < TM; i++)
#pragma unroll
        for (int j = 0; j < TN; j++) acc[i][j] = 0.0f;

    for (int k0 = 0; k0 < D_IN; k0 += BK) {
#pragma unroll
        for (int l = 0; l < 4; l++) {
            int e = tid + l * 256;
            int m = e >> 3;
            int k = e & 7;
            int g = k0 + k;
            float v = 0.0f;
            int gm = m0 + m;
            if (g < F_DIM)      v = state[(size_t)gm * F_DIM + g];
            else if (g < D_IN)  v = history[(size_t)gm * H_DIM + (g - F_DIM)];
            As[k][m] = v;
        }
#pragma unroll
        for (int l = 0; l < 4; l++) {
            int e = tid + l * 256;
            int n = e >> 3;
            int k = e & 7;
            int g = k0 + k;
            float v = 0.0f;
            if (g < D_IN) v = W1[(size_t)n * D_IN + g];
            Bs[k][n] = v;
        }
        __syncthreads();

#pragma unroll
        for (int k = 0; k < BK; k++) {
            float ra[TM], rb[TN];
#pragma unroll
            for (int i = 0; i < TM; i++) ra[i] = As[k][ty * TM + i];
#pragma unroll
            for (int j = 0; j < TN; j++) rb[j] = Bs[k][tx * TN + j];
#pragma unroll
            for (int i = 0; i < TM; i++)
#pragma unroll
                for (int j = 0; j < TN; j++)
                    acc[i][j] = fmaf(ra[i], rb[j], acc[i][j]);
        }
        __syncthreads();
    }

#pragma unroll
    for (int i = 0; i < TM; i++) {
        int m = m0 + ty * TM + i;
        float* dst = &g_h1[(size_t)m * N1 + tx * TN];
#pragma unroll
        for (int j = 0; j < TN; j++)
            dst[j] = acc[i][j] + b1[tx * TN + j];
    }
}

// ---------------------------------------------------------------------------
// Kernel R: layer-1 spike raster. Warp per sample; lane owns neurons q*32+lane.
// Identical LIF numerics to the previous (passing) in-loop version.
// ---------------------------------------------------------------------------
__global__ __launch_bounds__(256, 8)
void spike_raster_kernel()
{
    const int lane = threadIdx.x & 31;
    const int warp = threadIdx.x >> 5;
    const int s    = blockIdx.x * 8 + warp;

    float h[4], mem[4], syn[4];
#pragma unroll
    for (int q = 0; q < 4; q++) {
        h[q]   = g_h1[(size_t)s * N1 + q * 32 + lane];
        mem[q] = 0.0f;
        syn[q] = 0.0f;
    }

#pragma unroll
    for (int t = 0; t < T_STEPS; t++) {
        unsigned cur[4];
#pragma unroll
        for (int q = 0; q < 4; q++) {
            syn[q] = fmaf(ALPHA, syn[q], h[q]);
            mem[q] = fmaf(BETA,  mem[q], syn[q]);
            bool sp = (mem[q] - 1.0f) > 0.0f;
            cur[q] = __ballot_sync(0xffffffffu, sp);
            if (sp) mem[q] -= 1.0f;
        }
        if (lane == 0)
            g_spk[(size_t)s * T_STEPS + t] = make_uint4(cur[0], cur[1], cur[2], cur[3]);
    }
}

// ---------------------------------------------------------------------------
// Kernel 2: 10-step layer-2/3 recurrence, warp-per-sample, delta spike GEMVs.
// Layer-1 spikes come precomputed from g_spk. 1024 threads -> 32 warps/SM.
// ---------------------------------------------------------------------------
#define K2_THREADS 1024
#define W2_STRIDE 264    // 256 cols padded to 264 floats

__global__ __launch_bounds__(K2_THREADS, 1)
void snn_steps_kernel(const float* __restrict__ W2,
                      const float* __restrict__ b2,
                      const float* __restrict__ W3,
                      const float* __restrict__ b3,
                      float* __restrict__ out)
{
    extern __shared__ float sm[];
    float* W2c = sm;                                   // [128][264] col-major W2
    float* W3c = sm + (size_t)N1 * W2_STRIDE;          // [256][9]   col-major W3

    const int tid = threadIdx.x;

    for (int idx = tid; idx < N1 * N2; idx += K2_THREADS) {
        int i = idx & (N1 - 1);
        int j = idx >> 7;
        W2c[i * W2_STRIDE + j] = W2[idx];
    }
    for (int idx = tid; idx < N2 * N_OUT; idx += K2_THREADS) {
        int k = idx >> 8;
        int j = idx & (N2 - 1);
        W3c[j * N_OUT + k] = W3[idx];
    }
    __syncthreads();

    const int lane   = tid & 31;
    const int warp   = tid >> 5;
    const int gwarp  = blockIdx.x * (K2_THREADS / 32) + warp;
    const int nwarps = gridDim.x * (K2_THREADS / 32);

    const float4* b2v = reinterpret_cast<const float4*>(b2);

    for (int s = gwarp; s < B_SAMPLES; s += nwarps) {
        unsigned prev1[4] = {0u, 0u, 0u, 0u};

        // Layer-2 state: lane owns neurons j = lane*8 + r
        float h2a[8], mem2[8], syn2[8];
        float4 bb0 = b2v[lane * 2];
        float4 bb1 = b2v[lane * 2 + 1];
        h2a[0] = bb0.x; h2a[1] = bb0.y; h2a[2] = bb0.z; h2a[3] = bb0.w;
        h2a[4] = bb1.x; h2a[5] = bb1.y; h2a[6] = bb1.z; h2a[7] = bb1.w;
#pragma unroll
        for (int r = 0; r < 8; r++) { mem2[r] = 0.0f; syn2[r] = 0.0f; }
        unsigned prev2[8] = {0u,0u,0u,0u,0u,0u,0u,0u};

        // Layer-3 state: lanes 0..8 each own one output
        float h3a = (lane < N_OUT) ? b3[lane] : 0.0f;
        float syn3 = 0.0f, mem3 = 0.0f, pot = 0.0f;

        const uint4* spk = &g_spk[(size_t)s * T_STEPS];

        for (int t = 0; t < T_STEPS; t++) {
            // ---- Layer-1 spikes (precomputed, warp-uniform) ----
            uint4 m = spk[t];
            unsigned cur1[4] = {m.x, m.y, m.z, m.w};

            // ---- Delta update h2a += ± W2 columns for changed layer-1 neurons
#pragma unroll
            for (int q = 0; q < 4; q++) {
                unsigned chg = cur1[q] ^ prev1[q];
                prev1[q] = cur1[q];
                while (chg) {
                    int i = __ffs(chg) - 1; chg &= chg - 1;
                    float sgn = ((cur1[q] >> i) & 1u) ? 1.0f : -1.0f;
                    const float4* col = reinterpret_cast<const float4*>(
                        &W2c[(q * 32 + i) * W2_STRIDE + lane * 8]);
                    float4 a = col[0], b = col[1];
                    h2a[0] = fmaf(sgn, a.x, h2a[0]);
                    h2a[1] = fmaf(sgn, a.y, h2a[1]);
                    h2a[2] = fmaf(sgn, a.z, h2a[2]);
                    h2a[3] = fmaf(sgn, a.w, h2a[3]);
                    h2a[4] = fmaf(sgn, b.x, h2a[4]);
                    h2a[5] = fmaf(sgn, b.y, h2a[5]);
                    h2a[6] = fmaf(sgn, b.z, h2a[6]);
                    h2a[7] = fmaf(sgn, b.w, h2a[7]);
                }
            }

            // ---- LIF layer 2 ----
            unsigned cur2[8];
#pragma unroll
            for (int r = 0; r < 8; r++) {
                syn2[r] = fmaf(ALPHA, syn2[r], h2a[r]);
                mem2[r] = fmaf(BETA,  mem2[r], syn2[r]);
                bool sp = (mem2[r] - 1.0f) > 0.0f;
                cur2[r] = __ballot_sync(0xffffffffu, sp);
                if (sp) mem2[r] -= 1.0f;
            }

            // ---- Delta update h3a for changed layer-2 neurons ----
#pragma unroll
            for (int r = 0; r < 8; r++) {
                unsigned chg = cur2[r] ^ prev2[r];
                prev2[r] = cur2[r];
                while (chg) {
                    int l = __ffs(chg) - 1; chg &= chg - 1;
                    float sgn = ((cur2[r] >> l) & 1u) ? 1.0f : -1.0f;
                    if (lane < N_OUT)
                        h3a = fmaf(sgn, W3c[(l * 8 + r) * N_OUT + lane], h3a);
                }
            }

            // ---- Layer-3 integrate (no spike) ----
            syn3 = fmaf(ALPHA, syn3, h3a);
            mem3 = fmaf(BETA,  mem3, syn3);
            pot += mem3;
        }

        if (lane < N_OUT)
            out[(size_t)s * N_OUT + lane] = pot * (1.0f / T_STEPS);
    }
}

// ---------------------------------------------------------------------------
// Launch
// ---------------------------------------------------------------------------
extern "C" void kernel_launch(void* const* d_in, const int* in_sizes, int n_in,
                              void* d_out, int out_size)
{
    const float* state   = (const float*)d_in[0];
    const float* history = (const float*)d_in[1];
    const float* W1      = (const float*)d_in[2];
    const float* b1      = (const float*)d_in[3];
    const float* W2      = (const float*)d_in[4];
    const float* b2      = (const float*)d_in[5];
    const float* W3      = (const float*)d_in[6];
    const float* b3      = (const float*)d_in[7];
    float* out = (float*)d_out;

    // K1: h1 GEMM
    gemm_h1_kernel<<<B_SAMPLES / BM, 256>>>(state, history, W1, b1);

    // KR: layer-1 spike raster (warp per sample)
    spike_raster_kernel<<<B_SAMPLES / 8, 256>>>();

    // K2: layer-2/3 recurrence (144,384 B dynamic SMEM -> opt-in)
    const size_t smem_bytes = ((size_t)N1 * W2_STRIDE + (size_t)N2 * N_OUT) * sizeof(float);
    static bool attr_set = false;  // idempotent attribute set (not a work guard)
    if (!attr_set) {
        cudaFuncSetAttribute(snn_steps_kernel,
                             cudaFuncAttributeMaxDynamicSharedMemorySize,
                             (int)smem_bytes);
        attr_set = true;
    }
    snn_steps_kernel<<<148, K2_THREADS, smem_bytes>>>(W2, b2, W3, b3, out);
}

// round 6
// speedup vs baseline: 2.2769x; 1.9924x over previous
#include <cuda_runtime.h>
#include <cstdint>

#define B_SAMPLES 65536
#define F_DIM 512
#define H_DIM 90
#define D_IN 602
#define N1 128
#define N2 256
#define N_OUT 9
#define ALPHA 0.9f
#define BETA 0.8f
#define T_STEPS 10

// Packed layer-1 spike raster: per (sample, step) one uint4 = 128 spike bits.
__device__ uint4 g_spk[(size_t)B_SAMPLES * T_STEPS];

// pot = sum_t C[t] * h3(t);  C[t] = sum_{d=0}^{9-t} (beta^{d+1}-alpha^{d+1})/(beta-alpha)
__device__ __constant__ float d_C[T_STEPS] = {
    22.91390769f, 20.50086511f, 17.96883750f, 15.34188700f, 12.65607000f,
     9.96310000f,  7.33500000f,  4.87000000f,  2.70000000f,  1.00000000f
};
#define CSUM 115.2496673f

// ---------------------------------------------------------------------------
// Kernel 1: h1 = [state|history] @ W1^T + b1  (double-buffered fp32 SGEMM)
// + fused layer-1 LIF raster epilogue -> g_spk.   M=65536, N=128, K=602.
// ---------------------------------------------------------------------------
#define BM 128
#define BN 128
#define BK 16
#define NIT ((D_IN + BK - 1) / BK)   // 38
#define LDA 132                       // padded row stride (floats)
#define TILE_F (BK * LDA)             // 2112 floats per buffer

__global__ __launch_bounds__(256, 2)
void gemm_h1_raster_kernel(const float* __restrict__ state,
                           const float* __restrict__ history,
                           const float* __restrict__ W1,
                           const float* __restrict__ b1)
{
    extern __shared__ float sm[];
    // GEMM phase: As[2][16][132] at sm, Bs[2][16][132] at sm+2*TILE_F
    // Raster phase (after GEMM): h1s[128][132] aliases sm.
    float* Bbase = sm + 2 * TILE_F;

    const int tid = threadIdx.x;
    const int tx  = tid & 15;        // N direction
    const int ty  = tid >> 4;        // M direction
    const int m0  = blockIdx.x * BM;

    float acc[8][8];
#pragma unroll
    for (int i = 0; i < 8; i++)
#pragma unroll
        for (int j = 0; j < 8; j++) acc[i][j] = 0.0f;

    float rA[8], rB[8];

    // ---- prologue: load tile 0 straight to smem buffer 0 ----
#pragma unroll
    for (int l = 0; l < 8; l++) {
        int e = tid + l * 256;           // 0..2047
        int m = e >> 4;
        int k = e & 15;
        int g = k;                       // k0 = 0
        float v = 0.0f;
        int gm = m0 + m;
        if (g < F_DIM) v = state[(size_t)gm * F_DIM + g];
        sm[k * LDA + m] = v;             // As[0]
        float w = (g < D_IN) ? W1[(size_t)m * D_IN + g] : 0.0f;  // n = m here
        Bbase[k * LDA + m] = w;          // Bs[0]
    }
    __syncthreads();

    int buf = 0;
    for (int it = 0; it < NIT; it++) {
        // prefetch next tile gmem -> regs
        if (it + 1 < NIT) {
            int k0 = (it + 1) * BK;
#pragma unroll
            for (int l = 0; l < 8; l++) {
                int e = tid + l * 256;
                int m = e >> 4;
                int k = e & 15;
                int g = k0 + k;
                float v = 0.0f;
                int gm = m0 + m;
                if (g < F_DIM)      v = state[(size_t)gm * F_DIM + g];
                else if (g < D_IN)  v = history[(size_t)gm * H_DIM + (g - F_DIM)];
                rA[l] = v;
                rB[l] = (g < D_IN) ? W1[(size_t)m * D_IN + g] : 0.0f;
            }
        }

        // compute current buffer
        const float* Ac = sm    + buf * TILE_F;
        const float* Bc = Bbase + buf * TILE_F;
#pragma unroll
        for (int k = 0; k < BK; k++) {
            float4 a0 = *(const float4*)&Ac[k * LDA + ty * 8];
            float4 a1 = *(const float4*)&Ac[k * LDA + ty * 8 + 4];
            float4 b0 = *(const float4*)&Bc[k * LDA + tx * 8];
            float4 b1v = *(const float4*)&Bc[k * LDA + tx * 8 + 4];
            float ra[8] = {a0.x, a0.y, a0.z, a0.w, a1.x, a1.y, a1.z, a1.w};
            float rb[8] = {b0.x, b0.y, b0.z, b0.w, b1v.x, b1v.y, b1v.z, b1v.w};
#pragma unroll
            for (int i = 0; i < 8; i++)
#pragma unroll
                for (int j = 0; j < 8; j++)
                    acc[i][j] = fmaf(ra[i], rb[j], acc[i][j]);
        }

        // store prefetched tile into the other buffer
        if (it + 1 < NIT) {
            float* An = sm    + (buf ^ 1) * TILE_F;
            float* Bn = Bbase + (buf ^ 1) * TILE_F;
#pragma unroll
            for (int l = 0; l < 8; l++) {
                int e = tid + l * 256;
                int m = e >> 4;
                int k = e & 15;
                An[k * LDA + m] = rA[l];
                Bn[k * LDA + m] = rB[l];
            }
        }
        __syncthreads();
        buf ^= 1;
    }

    // ---- epilogue: bias add, stage h1 tile to smem ----
    float* h1s = sm;   // [128][132], aliases GEMM buffers (all reads done)
#pragma unroll
    for (int i = 0; i < 8; i++) {
        int row = ty * 8 + i;
#pragma unroll
        for (int j = 0; j < 8; j++)
            h1s[row * LDA + tx * 8 + j] = acc[i][j] + b1[tx * 8 + j];
    }
    __syncthreads();

    // ---- fused layer-1 LIF raster: warp w handles samples w*16..w*16+15 ----
    const int lane = tid & 31;
    const int warp = tid >> 5;
    for (int ml = warp * 16; ml < warp * 16 + 16; ml++) {
        const int s = m0 + ml;
        float h[4], mem[4], syn[4];
#pragma unroll
        for (int q = 0; q < 4; q++) {
            h[q]   = h1s[ml * LDA + q * 32 + lane];
            mem[q] = 0.0f;
            syn[q] = 0.0f;
        }
#pragma unroll
        for (int t = 0; t < T_STEPS; t++) {
            unsigned c[4];
#pragma unroll
            for (int q = 0; q < 4; q++) {
                syn[q] = fmaf(ALPHA, syn[q], h[q]);
                mem[q] = fmaf(BETA,  mem[q], syn[q]);
                bool sp = (mem[q] - 1.0f) > 0.0f;
                c[q] = __ballot_sync(0xffffffffu, sp);
                if (sp) mem[q] -= 1.0f;
            }
            if (lane == 0)
                g_spk[(size_t)s * T_STEPS + t] = make_uint4(c[0], c[1], c[2], c[3]);
        }
    }
}

// ---------------------------------------------------------------------------
// Kernel 2: layer-2 LIF + linearized layer-3. Warp-per-sample.
// W2 columns in smem with 16B-chunk swizzle (c ^= (c>>3)&1) -> conflict-free
// LDS.128 at 32B lane stride. Layer-3 folded into weighted spike sum z.
// ---------------------------------------------------------------------------
#define K2_THREADS 1024
#define W2_STRIDE 264    // 256 floats padded to 264

__device__ __forceinline__ int sw4(int j) {
    int c = j >> 2;
    c ^= (c >> 3) & 1;
    return (c << 2) | (j & 3);
}

__global__ __launch_bounds__(K2_THREADS, 1)
void snn_steps_kernel(const float* __restrict__ W2,
                      const float* __restrict__ b2,
                      const float* __restrict__ W3,
                      const float* __restrict__ b3,
                      float* __restrict__ out)
{
    extern __shared__ float smem[];
    float* W2c = smem;                                  // [128][264] swizzled cols
    float* W3r = smem + (size_t)N1 * W2_STRIDE;         // [9][264]   swizzled rows

    const int tid = threadIdx.x;

    for (int idx = tid; idx < N1 * N2; idx += K2_THREADS) {
        int i = idx & (N1 - 1);          // W2 row-major [256][128]: idx = j*128+i
        int j = idx >> 7;
        W2c[i * W2_STRIDE + sw4(j)] = W2[idx];
    }
    for (int idx = tid; idx < N_OUT * N2; idx += K2_THREADS) {
        int k = idx >> 8;                // W3 row-major [9][256]
        int j = idx & (N2 - 1);
        W3r[k * W2_STRIDE + sw4(j)] = W3[idx];
    }
    __syncthreads();

    const int lane   = tid & 31;
    const int warp   = tid >> 5;
    const int gwarp  = blockIdx.x * (K2_THREADS / 32) + warp;
    const int nwarps = gridDim.x * (K2_THREADS / 32);

    // per-lane swizzled float offsets for chunks 2*lane and 2*lane+1
    const int sbit = (lane >> 2) & 1;
    const int off0 = ((2 * lane)     ^ sbit) << 2;
    const int off1 = ((2 * lane + 1) ^ sbit) << 2;

    const float4* b2v = reinterpret_cast<const float4*>(b2);
    const float b3v = (lane < N_OUT) ? b3[lane] : 0.0f;

    for (int s = gwarp; s < B_SAMPLES; s += nwarps) {
        unsigned prev[4] = {0u, 0u, 0u, 0u};

        float h2a[8], mem2[8], syn2[8], z[8];
        float4 bb0 = b2v[lane * 2];
        float4 bb1 = b2v[lane * 2 + 1];
        h2a[0] = bb0.x; h2a[1] = bb0.y; h2a[2] = bb0.z; h2a[3] = bb0.w;
        h2a[4] = bb1.x; h2a[5] = bb1.y; h2a[6] = bb1.z; h2a[7] = bb1.w;
#pragma unroll
        for (int r = 0; r < 8; r++) { mem2[r] = 0.0f; syn2[r] = 0.0f; z[r] = 0.0f; }

        const uint4* spk = &g_spk[(size_t)s * T_STEPS];

#pragma unroll
        for (int t = 0; t < T_STEPS; t++) {
            uint4 mv = __ldg(&spk[t]);
            unsigned cur[4] = {mv.x, mv.y, mv.z, mv.w};

            // delta update of h2a for changed layer-1 neurons
#pragma unroll
            for (int q = 0; q < 4; q++) {
                unsigned chg = cur[q] ^ prev[q];
                prev[q] = cur[q];
                while (chg) {
                    int i = __ffs(chg) - 1; chg &= chg - 1;
                    float sgn = ((cur[q] >> i) & 1u) ? 1.0f : -1.0f;
                    const float* col = &W2c[(q * 32 + i) * W2_STRIDE];
                    float4 a = *(const float4*)&col[off0];
                    float4 b = *(const float4*)&col[off1];
                    h2a[0] = fmaf(sgn, a.x, h2a[0]);
                    h2a[1] = fmaf(sgn, a.y, h2a[1]);
                    h2a[2] = fmaf(sgn, a.z, h2a[2]);
                    h2a[3] = fmaf(sgn, a.w, h2a[3]);
                    h2a[4] = fmaf(sgn, b.x, h2a[4]);
                    h2a[5] = fmaf(sgn, b.y, h2a[5]);
                    h2a[6] = fmaf(sgn, b.z, h2a[6]);
                    h2a[7] = fmaf(sgn, b.w, h2a[7]);
                }
            }

            // LIF layer 2 + weighted spike accumulation for layer 3
            const float Ct = d_C[t];
#pragma unroll
            for (int r = 0; r < 8; r++) {
                syn2[r] = fmaf(ALPHA, syn2[r], h2a[r]);
                mem2[r] = fmaf(BETA,  mem2[r], syn2[r]);
                bool sp = (mem2[r] - 1.0f) > 0.0f;
                if (sp) { mem2[r] -= 1.0f; z[r] += Ct; }
            }
        }

        // final GEMV: p[k] = sum_j W3[k][j] * z_j   (per-lane partial, then reduce)
        float p[N_OUT];
#pragma unroll
        for (int k = 0; k < N_OUT; k++) {
            const float* row = &W3r[k * W2_STRIDE];
            float4 a = *(const float4*)&row[off0];
            float4 b = *(const float4*)&row[off1];
            float acc;
            acc = z[0] * a.x;
            acc = fmaf(z[1], a.y, acc);
            acc = fmaf(z[2], a.z, acc);
            acc = fmaf(z[3], a.w, acc);
            acc = fmaf(z[4], b.x, acc);
            acc = fmaf(z[5], b.y, acc);
            acc = fmaf(z[6], b.z, acc);
            acc = fmaf(z[7], b.w, acc);
            p[k] = acc;
        }
#pragma unroll
        for (int d = 16; d >= 1; d >>= 1)
#pragma unroll
            for (int k = 0; k < N_OUT; k++)
                p[k] += __shfl_xor_sync(0xffffffffu, p[k], d);

        if (lane < N_OUT)
            out[(size_t)s * N_OUT + lane] =
                (p[lane] + CSUM * b3v) * (1.0f / T_STEPS);
    }
}

// ---------------------------------------------------------------------------
// Launch
// ---------------------------------------------------------------------------
extern "C" void kernel_launch(void* const* d_in, const int* in_sizes, int n_in,
                              void* d_out, int out_size)
{
    const float* state   = (const float*)d_in[0];
    const float* history = (const float*)d_in[1];
    const float* W1      = (const float*)d_in[2];
    const float* b1      = (const float*)d_in[3];
    const float* W2      = (const float*)d_in[4];
    const float* b2      = (const float*)d_in[5];
    const float* W3      = (const float*)d_in[6];
    const float* b3      = (const float*)d_in[7];
    float* out = (float*)d_out;

    const size_t k1_smem = (size_t)BM * LDA * sizeof(float);              // 67584
    const size_t k2_smem = ((size_t)N1 + N_OUT) * W2_STRIDE * sizeof(float); // 144672

    static bool attr_set = false;   // idempotent attribute set (not a work guard)
    if (!attr_set) {
        cudaFuncSetAttribute(gemm_h1_raster_kernel,
                             cudaFuncAttributeMaxDynamicSharedMemorySize, (int)k1_smem);
        cudaFuncSetAttribute(snn_steps_kernel,
                             cudaFuncAttributeMaxDynamicSharedMemorySize, (int)k2_smem);
        attr_set = true;
    }

    // K1: h1 GEMM + fused layer-1 raster
    gemm_h1_raster_kernel<<<B_SAMPLES / BM, 256, k1_smem>>>(state, history, W1, b1);

    // K2: layer-2/3 recurrence
    snn_steps_kernel<<<148, K2_THREADS, k2_smem>>>(W2, b2, W3, b3, out);
}